// round 4
// baseline (speedup 1.0000x reference)
#include <cuda_runtime.h>
#include <cuda_bf16.h>
#include <cstdint>

// AxonalConnections: out[b,t] = sum_s adj[t,s] * (1.5*E[s]-0.5) * spikes[b,s]
// adj is conv-pattern sparse (9 taps per target, boundary-clipped).
//
// R4: 128 CTAs (one target ROW each; <=1 CTA/SM, perfectly balanced wave).
//   - Gather threads (384) issue adj+E loads FIRST (critical path).
//   - ALL threads then issue their 72 spike loads into registers (indices
//     are pure functions of t -> no dependency on the gather).
//   - Both memory trips are in flight concurrently; after the sync it is
//     pure FMA against smem-broadcast weights.

#define HW 128
#define S_TOT (HW * HW)      // 16384
#define B_TOT 32
#define TPC 128              // one full target row per CTA
#define THREADS 512          // 4 batch-groups x 128 target lanes
#define BPT 8                // batches per thread

__global__ __launch_bounds__(THREADS)
void axonal_r4_kernel(const float* __restrict__ spikes,   // [B, 16384]
                      const float* __restrict__ E,        // [16384]
                      const float* __restrict__ adj,      // [16384, 16384]
                      float* __restrict__ out)            // [B, 16384]
{
    __shared__ float wsm[9 * TPC];   // [k][tj] folded weights for this row

    const int tid = threadIdx.x;
    const int ti  = blockIdx.x;          // target row
    const int t0  = ti * HW;

    // ---- Gather (threads 0..383): 3 adjacent taps each, folded with E ----
    float gw[3];
    int   gk = -1, gtl = 0;
    if (tid < 3 * TPC) {
        gtl = tid & (TPC - 1);           // target column tj
        const int ki = tid >> 7;         // 0..2
        gk = ki;
        const int t  = t0 + gtl;
        const int si = ti - 1 + ki;
        const bool rowok = (si >= 0) & (si < HW);
        const size_t rowbase = (size_t)t * S_TOT + (size_t)(si * HW);
#pragma unroll
        for (int kj = 0; kj < 3; ++kj) {
            const int sj = gtl - 1 + kj;
            const bool ok = rowok & (sj >= 0) & (sj < HW);
            float w = 0.0f;
            if (ok) {
                const int s = si * HW + sj;
                w = __ldg(&adj[rowbase + (size_t)sj]) *
                    (1.5f * __ldg(&E[s]) - 0.5f);
            }
            gw[kj] = w;
        }
    }

    // ---- Everyone: compute own tap indices, issue ALL spike loads now ----
    const int tloc = tid & (TPC - 1);    // target column, coalesced per warp
    const int bg   = tid >> 7;           // 0..3 batch groups
    const int t    = t0 + tloc;

    int so[9];
#pragma unroll
    for (int k = 0; k < 9; ++k) {
        const int ki = k / 3, kj = k - 3 * ki;
        const int si = ti - 1 + ki;
        const int sj = tloc - 1 + kj;
        const bool ok = (si >= 0) & (si < HW) & (sj >= 0) & (sj < HW);
        so[k] = ok ? (si * HW + sj) : 0;     // clipped -> weight is 0 anyway
    }

    float sv[BPT][9];
#pragma unroll
    for (int bb = 0; bb < BPT; ++bb) {
        const float* __restrict__ sp = spikes + (size_t)(bg * BPT + bb) * S_TOT;
#pragma unroll
        for (int k = 0; k < 9; ++k)
            sv[bb][k] = __ldg(&sp[so[k]]);
    }

    // ---- Publish weights (gather loads have had maximum time in flight) ----
    if (gk >= 0) {
#pragma unroll
        for (int kj = 0; kj < 3; ++kj)
            wsm[(gk * 3 + kj) * TPC + gtl] = gw[kj];
    }
    __syncthreads();

    float w[9];
#pragma unroll
    for (int k = 0; k < 9; ++k)
        w[k] = wsm[k * TPC + tloc];      // broadcast, conflict-free

    // ---- Pure FMA + store ----
#pragma unroll
    for (int bb = 0; bb < BPT; ++bb) {
        float a0 = w[0] * sv[bb][0];
        float a1 = w[1] * sv[bb][1];
        float a2 = w[2] * sv[bb][2];
        a0 = fmaf(w[3], sv[bb][3], a0);
        a1 = fmaf(w[4], sv[bb][4], a1);
        a2 = fmaf(w[5], sv[bb][5], a2);
        a0 = fmaf(w[6], sv[bb][6], a0);
        a1 = fmaf(w[7], sv[bb][7], a1);
        a2 = fmaf(w[8], sv[bb][8], a2);
        out[(size_t)(bg * BPT + bb) * S_TOT + t] = a0 + a1 + a2;
    }
}

extern "C" void kernel_launch(void* const* d_in, const int* in_sizes, int n_in,
                              void* d_out, int out_size)
{
    // Identify inputs by element count:
    //   spikes: 524288, E: 16384, adjacency: 268435456
    const float* spikes = nullptr;
    const float* E      = nullptr;
    const float* adj    = nullptr;
    for (int i = 0; i < n_in; ++i) {
        if (in_sizes[i] == B_TOT * S_TOT)  spikes = (const float*)d_in[i];
        else if (in_sizes[i] == S_TOT)     E      = (const float*)d_in[i];
        else                               adj    = (const float*)d_in[i];
    }
    float* out = (float*)d_out;

    axonal_r4_kernel<<<HW, THREADS>>>(spikes, E, adj, out);  // 128 CTAs
}